// round 10
// baseline (speedup 1.0000x reference)
#include <cuda_runtime.h>
#include <cstdint>

// ---------------- problem constants ----------------
#define BB   64      // batch
#define TT   512     // seq len
#define EE   256     // embed dim
#define HH   512     // hidden
#define GH   2048    // 4*H
#define CD   4       // classes

// ---------------- scan configuration ----------------
#define NCG  16                 // column groups (32 h-cols each, all 4 gates)
#define NKS  8                  // k splits (64 k each)
#define GRID_SCAN (NCG * NKS)   // 128 persistent CTAs (<= 148 SMs -> co-resident wave 1)
#define KC   64                 // k per chunk
#define WROW 66                 // padded W smem row (floats) = 33 ull -> conflict-free LDS.64
#define SMEM_SCAN ((128 * WROW + BB * KC) * 4)   // 50176 bytes dynamic smem

typedef unsigned long long ull;

// ---------------- device scratch (static: no allocs allowed) ----------------
__device__ float    d_xg[(size_t)TT * BB * GH];        // 256 MB: xg[(t*64+b)*2048 + g]
__device__ float    d_hbuf[BB * HH];                   // hidden state h[b][k]
__device__ float    d_part[NCG * NKS * 128 * BB];      // 4 MB: partial[(cg,ks)][row(0..127)][b]
__device__ unsigned d_cnt;                             // grid-barrier arrivals (monotonic per launch)
__device__ unsigned d_rel;                             // grid-barrier release index

// ---------------- helpers ----------------
__device__ __forceinline__ void ffma2(ull& d, ull a, ull b) {
    // packed f32x2 FMA: d.lo += a.lo*b.lo ; d.hi += a.hi*b.hi
    asm("fma.rn.f32x2 %0, %1, %2, %0;" : "+l"(d) : "l"(a), "l"(b));
}
__device__ __forceinline__ float hadd2(ull u) {
    float lo = __uint_as_float((unsigned)(u & 0xffffffffull));
    float hi = __uint_as_float((unsigned)(u >> 32));
    return lo + hi;
}
__device__ __forceinline__ float sigf(float v) {
    return 1.0f / (1.0f + __expf(-v));
}

// software grid barrier, monotonic counters; idx = 1,2,3,...
__device__ __forceinline__ void gbar(unsigned idx) {
    __threadfence();            // every thread: publish my global writes
    __syncthreads();
    if (threadIdx.x == 0) {
        unsigned prev = atomicAdd(&d_cnt, 1u);
        if (prev == idx * (unsigned)GRID_SCAN - 1u) {
            atomicExch(&d_rel, idx);                       // release
        } else {
            while (*(volatile unsigned*)&d_rel < idx) __nanosleep(64);
        }
        __threadfence();
    }
    __syncthreads();
}

// ---------------- kernel 0: per-launch reset (graph replays must be deterministic) ----
__global__ void init_kernel() {
    int i = blockIdx.x * blockDim.x + threadIdx.x;
    if (i == 0) { d_cnt = 0u; d_rel = 0u; }
    for (int j = i; j < BB * HH; j += gridDim.x * blockDim.x) d_hbuf[j] = 0.0f;
}

// ---------------- kernel 1: fused embedding gather + input GEMM -----------------------
// xg[(t*64+b)][n] = emb[x[b][t]] . W_ih[n] + (b_ih[n] + b_hh[n])
// Tile: 64 rows (= one t, b = 0..63) x 64 cols, K-tile 16, 256 threads, 4x4 microtile.
__global__ void __launch_bounds__(256) emb_gemm_kernel(
    const int*   __restrict__ x,
    const float* __restrict__ emb,
    const float* __restrict__ W_ih,
    const float* __restrict__ b_ih,
    const float* __restrict__ b_hh)
{
    __shared__ float As[16][68];
    __shared__ float Bs[16][68];
    const int tid  = threadIdx.x;
    const int n0   = blockIdx.x * 64;
    const int tblk = blockIdx.y;                   // sequence position t
    const int rowL = tid >> 2;                     // 0..63
    const int kq   = (tid & 3) * 4;                // 0,4,8,12

    const float* aptr = emb  + (size_t)x[rowL * TT + tblk] * EE + kq;  // b=rowL, t=tblk
    const float* bptr = W_ih + (size_t)(n0 + rowL) * EE + kq;

    const int tx = tid & 15, ty = tid >> 4;
    float acc[4][4];
#pragma unroll
    for (int i = 0; i < 4; ++i)
#pragma unroll
        for (int j = 0; j < 4; ++j) acc[i][j] = 0.0f;

    for (int kt = 0; kt < EE; kt += 16) {
        float4 a  = *(const float4*)(aptr + kt);
        float4 bv = *(const float4*)(bptr + kt);
        __syncthreads();
        As[kq + 0][rowL] = a.x;  As[kq + 1][rowL] = a.y;
        As[kq + 2][rowL] = a.z;  As[kq + 3][rowL] = a.w;
        Bs[kq + 0][rowL] = bv.x; Bs[kq + 1][rowL] = bv.y;
        Bs[kq + 2][rowL] = bv.z; Bs[kq + 3][rowL] = bv.w;
        __syncthreads();
#pragma unroll
        for (int k = 0; k < 16; ++k) {
            float4 av = *(const float4*)&As[k][ty * 4];
            float4 bw = *(const float4*)&Bs[k][tx * 4];
            float ar[4] = {av.x, av.y, av.z, av.w};
            float br[4] = {bw.x, bw.y, bw.z, bw.w};
#pragma unroll
            for (int i = 0; i < 4; ++i)
#pragma unroll
                for (int j = 0; j < 4; ++j) acc[i][j] += ar[i] * br[j];
        }
    }

    const int n = n0 + tx * 4;
    float4 bias;
    bias.x = b_ih[n + 0] + b_hh[n + 0];
    bias.y = b_ih[n + 1] + b_hh[n + 1];
    bias.z = b_ih[n + 2] + b_hh[n + 2];
    bias.w = b_ih[n + 3] + b_hh[n + 3];
#pragma unroll
    for (int i = 0; i < 4; ++i) {
        float4 r;
        r.x = acc[i][0] + bias.x; r.y = acc[i][1] + bias.y;
        r.z = acc[i][2] + bias.z; r.w = acc[i][3] + bias.w;
        *(float4*)(d_xg + ((size_t)tblk * 64 + ty * 4 + i) * GH + n) = r;
    }
}

// ---------------- kernel 2: persistent LSTM scan ---------------------------------------
// CTA (cg, ks): cg = blockIdx.x & 15 owns h-cols [cg*32, cg*32+32) for all 4 gates
// (CTA-local row r = q*32 + c -> global gate row q*512 + cg*32 + c), ks = blockIdx.x >> 4
// owns k in [ks*64, ks*64+64). Thread (bg = tid>>5, rg = tid&31) computes rows
// {q*32 + rg : q=0..3} for batches b0..b0+7 (b0 = bg*8). ks==0 CTAs reduce + gate.
__global__ void __launch_bounds__(256, 1) scan_kernel(const float* __restrict__ W_hh) {
    extern __shared__ float sm[];
    float* sm_w = sm;                    // [128][WROW]
    float* sm_h = sm + 128 * WROW;       // [64][KC]

    const int tid = threadIdx.x;
    const int cg  = blockIdx.x & (NCG - 1);
    const int ks  = blockIdx.x >> 4;
    const int rg  = tid & 31;
    const int bg  = tid >> 5;
    const int b0  = bg * 8;

    // Load W_hh slice once; reused for all 512 steps.
    for (int idx = tid; idx < 128 * KC; idx += 256) {
        int r = idx >> 6, k = idx & 63;
        int grow = (r >> 5) * HH + cg * 32 + (r & 31);     // gate q = r>>5, col c = r&31
        sm_w[r * WROW + k] = W_hh[(size_t)grow * HH + ks * KC + k];
    }

    float creg[8];                                          // cell state (ks==0 only)
#pragma unroll
    for (int j = 0; j < 8; ++j) creg[j] = 0.0f;

    const ull* Ws2 = (const ull*)sm_w;                      // row stride 33 ull
    const ull* Hs2 = (const ull*)sm_h;                      // row stride 32 ull
    unsigned bar = 0;

    for (int t = 0; t < TT; ++t) {
        // --- stage h chunk (cross-SM data: must bypass stale persistent L1) ---
#pragma unroll
        for (int v = 0; v < 4; ++v) {
            int fidx = tid * 16 + v * 4;
            int b = fidx >> 6, k = fidx & 63;
            float4 hv = __ldcg((const float4*)(d_hbuf + b * HH + ks * KC + k));
            *(float4*)(sm_h + b * KC + k) = hv;
        }
        __syncthreads();     // also covers the one-time W load on t==0

        // --- partial GEMV: acc[q][j] = (pairwise over k) W[q*32+rg] . h[b0+j] ---
        ull acc[4][8];
#pragma unroll
        for (int q = 0; q < 4; ++q)
#pragma unroll
            for (int j = 0; j < 8; ++j) acc[q][j] = 0ull;

#pragma unroll 4
        for (int k2 = 0; k2 < 32; ++k2) {
            ull w0 = Ws2[(rg     ) * 33 + k2];
            ull w1 = Ws2[(rg + 32) * 33 + k2];
            ull w2 = Ws2[(rg + 64) * 33 + k2];
            ull w3 = Ws2[(rg + 96) * 33 + k2];
            const ull* hp = Hs2 + b0 * 32 + k2;
#pragma unroll
            for (int j = 0; j < 8; ++j) {
                ull hv = hp[j * 32];
                ffma2(acc[0][j], w0, hv);
                ffma2(acc[1][j], w1, hv);
                ffma2(acc[2][j], w2, hv);
                ffma2(acc[3][j], w3, hv);
            }
        }

        if (ks != 0) {
            // publish partials, then idle through both barriers
            float* pb = d_part + (size_t)((cg * NKS + ks) * 128) * BB;
#pragma unroll
            for (int q = 0; q < 4; ++q) {
                float v0 = hadd2(acc[q][0]), v1 = hadd2(acc[q][1]);
                float v2 = hadd2(acc[q][2]), v3 = hadd2(acc[q][3]);
                float v4 = hadd2(acc[q][4]), v5 = hadd2(acc[q][5]);
                float v6 = hadd2(acc[q][6]), v7 = hadd2(acc[q][7]);
                float* dst = pb + (q * 32 + rg) * BB + b0;
                *(float4*)(dst)     = make_float4(v0, v1, v2, v3);
                *(float4*)(dst + 4) = make_float4(v4, v5, v6, v7);
            }
            gbar(++bar);
            gbar(++bar);
        } else {
            float gp[4][8];
#pragma unroll
            for (int q = 0; q < 4; ++q)
#pragma unroll
                for (int j = 0; j < 8; ++j) gp[q][j] = hadd2(acc[q][j]);

            // add precomputed input-side gates
            const float* xgp = d_xg + (size_t)t * BB * GH;
#pragma unroll
            for (int q = 0; q < 4; ++q) {
                int grow = q * HH + cg * 32 + rg;
#pragma unroll
                for (int j = 0; j < 8; ++j)
                    gp[q][j] += __ldg(xgp + (size_t)(b0 + j) * GH + grow);
            }

            gbar(++bar);     // partials now visible

            for (int k = 1; k < NKS; ++k) {
                const float* pb = d_part + (size_t)((cg * NKS + k) * 128) * BB;
#pragma unroll
                for (int q = 0; q < 4; ++q) {
                    const float4* p = (const float4*)(pb + (q * 32 + rg) * BB + b0);
                    float4 u0 = __ldcg(p);
                    float4 u1 = __ldcg(p + 1);
                    gp[q][0] += u0.x; gp[q][1] += u0.y; gp[q][2] += u0.z; gp[q][3] += u0.w;
                    gp[q][4] += u1.x; gp[q][5] += u1.y; gp[q][6] += u1.z; gp[q][7] += u1.w;
                }
            }

            const int col = cg * 32 + rg;
#pragma unroll
            for (int j = 0; j < 8; ++j) {
                float ig = sigf(gp[0][j]);
                float fg = sigf(gp[1][j]);
                float gg = tanhf(gp[2][j]);
                float og = sigf(gp[3][j]);
                creg[j] = fg * creg[j] + ig * gg;
                d_hbuf[(b0 + j) * HH + col] = og * tanhf(creg[j]);
            }

            gbar(++bar);     // new h visible to all CTAs
        }
    }
}

// ---------------- kernel 3: final FC (64x4x512, trivial) -------------------------------
__global__ void fc_kernel(const float* __restrict__ W_fc,
                          const float* __restrict__ b_fc,
                          float* __restrict__ out)
{
    const int b    = blockIdx.x;
    const int w    = threadIdx.x >> 5;   // class 0..3
    const int lane = threadIdx.x & 31;
    const float* hb = d_hbuf + b * HH;
    const float* wf = W_fc + w * HH;
    float s = 0.0f;
    for (int k = lane; k < HH; k += 32) s += hb[k] * wf[k];
#pragma unroll
    for (int o = 16; o; o >>= 1) s += __shfl_down_sync(0xffffffffu, s, o);
    if (lane == 0) out[b * CD + w] = s + b_fc[w];
}

// ---------------- host launcher ---------------------------------------------------------
extern "C" void kernel_launch(void* const* d_in, const int* in_sizes, int n_in,
                              void* d_out, int out_size) {
    const int*   x    = (const int*)  d_in[0];
    const float* emb  = (const float*)d_in[1];
    const float* W_ih = (const float*)d_in[2];
    const float* W_hh = (const float*)d_in[3];
    const float* b_ih = (const float*)d_in[4];
    const float* b_hh = (const float*)d_in[5];
    const float* W_fc = (const float*)d_in[6];
    const float* b_fc = (const float*)d_in[7];
    float* out = (float*)d_out;

    cudaFuncSetAttribute(scan_kernel, cudaFuncAttributeMaxDynamicSharedMemorySize, SMEM_SCAN);

    init_kernel<<<64, 256>>>();
    emb_gemm_kernel<<<dim3(GH / 64, TT), 256>>>(x, emb, W_ih, b_ih, b_hh);
    scan_kernel<<<GRID_SCAN, 256, SMEM_SCAN>>>(W_hh);
    fc_kernel<<<BB, 128>>>(W_fc, b_fc, out);
}

// round 11
// speedup vs baseline: 1.0096x; 1.0096x over previous
#include <cuda_runtime.h>
#include <cstdint>

// ---------------- problem constants ----------------
#define BB   64      // batch
#define TT   512     // seq len
#define EE   256     // embed dim
#define HH   512     // hidden
#define GH   2048    // 4*H
#define CD   4       // classes

// ---------------- scan configuration ----------------
#define NCG  16                 // column groups (32 h-cols each, all 4 gates)
#define NKS  8                  // k splits (64 k each)
#define GRID_SCAN (NCG * NKS)   // 128 persistent CTAs, 1 per SM
#define KC   64                 // k per chunk
#define WROW 66                 // padded W smem row (floats) = 33 ull -> conflict-free LDS.64
#define SMEM_SCAN ((128 * WROW + BB * KC) * 4)   // 50176 B dynamic smem

typedef unsigned long long ull;

#define PSLOT ((size_t)NCG * NKS * 128 * BB)     // floats per partial slot
#define HSLOT ((size_t)BB * HH)                  // floats per h slot

// ---------------- device scratch (no allocs allowed) ----------------
__device__ float    d_xg[(size_t)TT * BB * GH];   // 256 MB: xg[(t*64+b)*2048 + g]
__device__ float    d_hbuf[2 * BB * HH];          // double-buffered h: slot t&1 holds h_t
__device__ float    d_part[2 * NCG * NKS * 128 * BB];  // 8 MB double-buffered partials
__device__ unsigned d_hflag[NCG];                 // = t+1 after h_{t+1} written by cg's ks0
__device__ unsigned d_pflag[NCG * NKS];           // = t+1 after partial of step t published

// ---------------- helpers ----------------
__device__ __forceinline__ void ffma2(ull& d, ull a, ull b) {
    asm("fma.rn.f32x2 %0, %1, %2, %0;" : "+l"(d) : "l"(a), "l"(b));
}
__device__ __forceinline__ float hadd2(ull u) {
    float lo = __uint_as_float((unsigned)(u & 0xffffffffull));
    float hi = __uint_as_float((unsigned)(u >> 32));
    return lo + hi;
}
__device__ __forceinline__ float tanhfast(float x) {
    float r; asm("tanh.approx.f32 %0, %1;" : "=f"(r) : "f"(x)); return r;
}
__device__ __forceinline__ float sigfast(float x) {
    return fmaf(tanhfast(0.5f * x), 0.5f, 0.5f);
}

// ---------------- kernel 0: per-launch reset (graph replays must be deterministic) ----
__global__ void init_kernel() {
    int i = blockIdx.x * blockDim.x + threadIdx.x;
    if (i < NCG) d_hflag[i] = 0u;
    if (i < NCG * NKS) d_pflag[i] = 0u;
    for (int j = i; j < BB * HH; j += gridDim.x * blockDim.x) d_hbuf[j] = 0.0f;  // h_0 = 0 (slot 0)
}

// ---------------- kernel 1: fused embedding gather + input GEMM -----------------------
// xg[(t*64+b)][n] = emb[x[b][t]] . W_ih[n] + (b_ih[n] + b_hh[n])
// 128(M) x 64(N) tile, K-tile 16, 256 threads, 8x4 microtile.
__global__ void __launch_bounds__(256) emb_gemm_kernel(
    const int*   __restrict__ x,
    const float* __restrict__ emb,
    const float* __restrict__ W_ih,
    const float* __restrict__ b_ih,
    const float* __restrict__ b_hh)
{
    __shared__ float As[16][132];
    __shared__ float Bs[16][68];
    const int tid = threadIdx.x;
    const int m0  = blockIdx.y * 128;
    const int n0  = blockIdx.x * 64;

    // A loader: row rA = tid>>1 (0..127), k-octet kA = (tid&1)*8
    const int rA = tid >> 1, kA = (tid & 1) * 8;
    const int tpos = (m0 + rA) >> 6, bpos = rA & 63;
    const float* aptr = emb + (size_t)x[bpos * TT + tpos] * EE + kA;
    // B loader: row rB = tid>>2 (0..63), k-quad kB = (tid&3)*4
    const int rB = tid >> 2, kB = (tid & 3) * 4;
    const float* bptr = W_ih + (size_t)(n0 + rB) * EE + kB;

    const int tx = tid & 15, ty = tid >> 4;
    float acc[8][4];
#pragma unroll
    for (int i = 0; i < 8; ++i)
#pragma unroll
        for (int j = 0; j < 4; ++j) acc[i][j] = 0.0f;

    for (int kt = 0; kt < EE; kt += 16) {
        float4 a0 = *(const float4*)(aptr + kt);
        float4 a1 = *(const float4*)(aptr + kt + 4);
        float4 bv = *(const float4*)(bptr + kt);
        __syncthreads();
        As[kA + 0][rA] = a0.x; As[kA + 1][rA] = a0.y;
        As[kA + 2][rA] = a0.z; As[kA + 3][rA] = a0.w;
        As[kA + 4][rA] = a1.x; As[kA + 5][rA] = a1.y;
        As[kA + 6][rA] = a1.z; As[kA + 7][rA] = a1.w;
        Bs[kB + 0][rB] = bv.x; Bs[kB + 1][rB] = bv.y;
        Bs[kB + 2][rB] = bv.z; Bs[kB + 3][rB] = bv.w;
        __syncthreads();
#pragma unroll
        for (int k = 0; k < 16; ++k) {
            float4 av0 = *(const float4*)&As[k][ty * 8];
            float4 av1 = *(const float4*)&As[k][ty * 8 + 4];
            float4 bw  = *(const float4*)&Bs[k][tx * 4];
            float ar[8] = {av0.x, av0.y, av0.z, av0.w, av1.x, av1.y, av1.z, av1.w};
            float br[4] = {bw.x, bw.y, bw.z, bw.w};
#pragma unroll
            for (int i = 0; i < 8; ++i)
#pragma unroll
                for (int j = 0; j < 4; ++j) acc[i][j] = fmaf(ar[i], br[j], acc[i][j]);
        }
    }

    const int n = n0 + tx * 4;
    float4 bias;
    bias.x = b_ih[n + 0] + b_hh[n + 0];
    bias.y = b_ih[n + 1] + b_hh[n + 1];
    bias.z = b_ih[n + 2] + b_hh[n + 2];
    bias.w = b_ih[n + 3] + b_hh[n + 3];
#pragma unroll
    for (int i = 0; i < 8; ++i) {
        float4 r;
        r.x = acc[i][0] + bias.x; r.y = acc[i][1] + bias.y;
        r.z = acc[i][2] + bias.z; r.w = acc[i][3] + bias.w;
        *(float4*)(d_xg + (size_t)(m0 + ty * 8 + i) * GH + n) = r;
    }
}

// ---------------- kernel 2: persistent LSTM scan (point-to-point flags) ----------------
// CTA (cg = bid&15, ks = bid>>4): cg owns h-cols [cg*32, cg*32+32) for all 4 gates,
// ks owns k in [ks*64, ks*64+64). Thread (bg = tid>>5, rg = tid&31) computes rows
// {q*32+rg : q<4} for batches b0..b0+7. ks==0 additionally reduces + gates + writes h.
// Sync: consumer of h chunk waits d_hflag[2ks],[2ks+1] >= t; reducer waits
// d_pflag[cg][1..7] >= t+1. h and partials double-buffered by t&1 (skew provably < 2).
__global__ void __launch_bounds__(256, 1) scan_kernel(const float* __restrict__ W_hh) {
    extern __shared__ float sm[];
    float* sm_w = sm;                    // [128][WROW]
    float* sm_h = sm + 128 * WROW;       // [64][KC]

    const int tid = threadIdx.x;
    const int cg  = blockIdx.x & (NCG - 1);
    const int ks  = blockIdx.x >> 4;
    const int rg  = tid & 31;
    const int bg  = tid >> 5;
    const int b0  = bg * 8;

    // W_hh slice -> smem once; reused for all 512 steps.
    for (int idx = tid; idx < 128 * KC; idx += 256) {
        int r = idx >> 6, k = idx & 63;
        int grow = (r >> 5) * HH + cg * 32 + (r & 31);
        sm_w[r * WROW + k] = W_hh[(size_t)grow * HH + ks * KC + k];
    }

    float creg[8];
#pragma unroll
    for (int j = 0; j < 8; ++j) creg[j] = 0.0f;

    const ull* Ws2 = (const ull*)sm_w;   // row stride 33 ull
    const ull* Hs2 = (const ull*)sm_h;   // row stride 32 ull

    for (int t = 0; t < TT; ++t) {
        // --- wait for h_t chunk producers (2 per-cg flags) ---
        if (tid < 2) {
            const int c = 2 * ks + tid;
            while (*(volatile unsigned*)&d_hflag[c] < (unsigned)t) { }
            __threadfence();             // acquire
        }
        __syncthreads();                 // also covers one-time W load at t==0

        // --- stage h_t chunk (L2-coherent loads; L1 is stale across SMs) ---
        const float* hsrc = d_hbuf + (size_t)(t & 1) * HSLOT + ks * KC;
#pragma unroll
        for (int v = 0; v < 4; ++v) {
            int fidx = tid * 16 + v * 4;
            int b = fidx >> 6, k = fidx & 63;
            float4 hv = __ldcg((const float4*)(hsrc + b * HH + k));
            *(float4*)(sm_h + b * KC + k) = hv;
        }
        __syncthreads();

        // --- prefetch xg for the reducer (independent of h; hides DRAM latency) ---
        float xr[4][8];
        if (ks == 0) {
            const float* xgp = d_xg + (size_t)t * BB * GH;
#pragma unroll
            for (int q = 0; q < 4; ++q) {
                int grow = q * HH + cg * 32 + rg;
#pragma unroll
                for (int j = 0; j < 8; ++j)
                    xr[q][j] = __ldg(xgp + (size_t)(b0 + j) * GH + grow);
            }
        }

        // --- partial GEMV: acc[q][j] = pairwise-k  W[q*32+rg] . h[b0+j] ---
        ull acc[4][8];
#pragma unroll
        for (int q = 0; q < 4; ++q)
#pragma unroll
            for (int j = 0; j < 8; ++j) acc[q][j] = 0ull;

#pragma unroll 4
        for (int k2 = 0; k2 < 32; ++k2) {
            ull w0 = Ws2[(rg     ) * 33 + k2];
            ull w1 = Ws2[(rg + 32) * 33 + k2];
            ull w2 = Ws2[(rg + 64) * 33 + k2];
            ull w3 = Ws2[(rg + 96) * 33 + k2];
            const ull* hp = Hs2 + b0 * 32 + k2;
#pragma unroll
            for (int j = 0; j < 8; ++j) {
                ull hv = hp[j * 32];
                ffma2(acc[0][j], w0, hv);
                ffma2(acc[1][j], w1, hv);
                ffma2(acc[2][j], w2, hv);
                ffma2(acc[3][j], w3, hv);
            }
        }

        if (ks != 0) {
            // publish partial into slot t&1, then release flag
            float* pb = d_part + (size_t)(t & 1) * PSLOT + (size_t)((cg * NKS + ks) * 128) * BB;
#pragma unroll
            for (int q = 0; q < 4; ++q) {
                float v0 = hadd2(acc[q][0]), v1 = hadd2(acc[q][1]);
                float v2 = hadd2(acc[q][2]), v3 = hadd2(acc[q][3]);
                float v4 = hadd2(acc[q][4]), v5 = hadd2(acc[q][5]);
                float v6 = hadd2(acc[q][6]), v7 = hadd2(acc[q][7]);
                float* dst = pb + (q * 32 + rg) * BB + b0;
                *(float4*)(dst)     = make_float4(v0, v1, v2, v3);
                *(float4*)(dst + 4) = make_float4(v4, v5, v6, v7);
            }
            __threadfence();
            __syncthreads();
            if (tid == 0) *(volatile unsigned*)&d_pflag[cg * NKS + ks] = (unsigned)(t + 1);
        } else {
            float gp[4][8];
#pragma unroll
            for (int q = 0; q < 4; ++q)
#pragma unroll
                for (int j = 0; j < 8; ++j) gp[q][j] = hadd2(acc[q][j]) + xr[q][j];

            // wait for the 7 sibling partials of this cg
            if (tid < 7) {
                while (*(volatile unsigned*)&d_pflag[cg * NKS + 1 + tid] < (unsigned)(t + 1)) { }
                __threadfence();         // acquire
            }
            __syncthreads();

            const float* ps = d_part + (size_t)(t & 1) * PSLOT;
            for (int k = 1; k < NKS; ++k) {
                const float* pb = ps + (size_t)((cg * NKS + k) * 128) * BB;
#pragma unroll
                for (int q = 0; q < 4; ++q) {
                    const float4* p = (const float4*)(pb + (q * 32 + rg) * BB + b0);
                    float4 u0 = __ldcg(p);
                    float4 u1 = __ldcg(p + 1);
                    gp[q][0] += u0.x; gp[q][1] += u0.y; gp[q][2] += u0.z; gp[q][3] += u0.w;
                    gp[q][4] += u1.x; gp[q][5] += u1.y; gp[q][6] += u1.z; gp[q][7] += u1.w;
                }
            }

            // gates (HW tanh), cell update, write h_{t+1} into slot (t+1)&1
            float* hdst = d_hbuf + (size_t)((t + 1) & 1) * HSLOT;
            const int col = cg * 32 + rg;
#pragma unroll
            for (int j = 0; j < 8; ++j) {
                float ig = sigfast(gp[0][j]);
                float fg = sigfast(gp[1][j]);
                float gg = tanhfast(gp[2][j]);
                float og = sigfast(gp[3][j]);
                creg[j] = fg * creg[j] + ig * gg;
                hdst[(b0 + j) * HH + col] = og * tanhfast(creg[j]);
            }
            __threadfence();
            __syncthreads();
            if (tid == 0) *(volatile unsigned*)&d_hflag[cg] = (unsigned)(t + 1);
        }
    }
}

// ---------------- kernel 3: final FC (64x4x512) ----------------------------------------
__global__ void fc_kernel(const float* __restrict__ W_fc,
                          const float* __restrict__ b_fc,
                          float* __restrict__ out)
{
    const int b    = blockIdx.x;
    const int w    = threadIdx.x >> 5;   // class 0..3
    const int lane = threadIdx.x & 31;
    const float* hb = d_hbuf + (size_t)(TT & 1) * HSLOT + b * HH;  // h_512 lives in slot 0
    const float* wf = W_fc + w * HH;
    float s = 0.0f;
    for (int k = lane; k < HH; k += 32) s += hb[k] * wf[k];
#pragma unroll
    for (int o = 16; o; o >>= 1) s += __shfl_down_sync(0xffffffffu, s, o);
    if (lane == 0) out[b * CD + w] = s + b_fc[w];
}

// ---------------- host launcher ---------------------------------------------------------
extern "C" void kernel_launch(void* const* d_in, const int* in_sizes, int n_in,
                              void* d_out, int out_size) {
    const int*   x    = (const int*)  d_in[0];
    const float* emb  = (const float*)d_in[1];
    const float* W_ih = (const float*)d_in[2];
    const float* W_hh = (const float*)d_in[3];
    const float* b_ih = (const float*)d_in[4];
    const float* b_hh = (const float*)d_in[5];
    const float* W_fc = (const float*)d_in[6];
    const float* b_fc = (const float*)d_in[7];
    float* out = (float*)d_out;

    cudaFuncSetAttribute(scan_kernel, cudaFuncAttributeMaxDynamicSharedMemorySize, SMEM_SCAN);

    init_kernel<<<64, 256>>>();
    emb_gemm_kernel<<<dim3(GH / 64, (BB * TT) / 128), 256>>>(x, emb, W_ih, b_ih, b_hh);
    scan_kernel<<<GRID_SCAN, 256, SMEM_SCAN>>>(W_hh);
    fc_kernel<<<BB, 128>>>(W_fc, b_fc, out);
}

// round 12
// speedup vs baseline: 1.1488x; 1.1379x over previous
#include <cuda_runtime.h>
#include <cstdint>

// ---------------- problem constants ----------------
#define BB   64      // batch
#define TT   512     // seq len
#define EE   256     // embed dim
#define HH   512     // hidden
#define GH   2048    // 4*H
#define CD   4       // classes

// ---------------- scan configuration ----------------
#define NCG  16                 // column groups (32 h-cols each, all 4 gates)
#define NKS  8                  // k splits (64 k each)
#define GRID_SCAN (NCG * NKS)   // 128 persistent CTAs, 1 per SM
#define KC   64                 // k per chunk
#define WROW 66                 // padded W smem row (floats) = 33 ull (odd -> conflict-free LDS.64)
#define SMEM_SCAN ((128 * WROW + BB * KC) * 4)   // 50176 B dynamic smem

typedef unsigned long long ull;

#define PSLOT ((size_t)NCG * NKS * 128 * BB)     // floats per partial slot
#define HSLOT ((size_t)BB * HH)                  // floats per h slot

// ---------------- device scratch (no allocs allowed) ----------------
// Each flag on its OWN 256B line: same-address L2 contention was the R10/R11 killer.
struct alignas(256) PadFlag { unsigned v; unsigned pad[63]; };

__device__ float   d_xg[(size_t)TT * BB * GH];        // 256 MB: xg[(t*64+b)*2048 + g]
__device__ float   d_hbuf[2 * BB * HH];               // double-buffered h: slot t&1 holds h_t
__device__ float   d_part[2 * NCG * NKS * 128 * BB];  // 8 MB double-buffered partials
__device__ PadFlag d_hflag[NCG];                      // v = t+1 after h_{t+1} written by cg's ks0
__device__ PadFlag d_pflag[NCG * NKS];                // v = t+1 after partial of step t published

// ---------------- helpers ----------------
__device__ __forceinline__ void ffma2(ull& d, ull a, ull b) {
    asm("fma.rn.f32x2 %0, %1, %2, %0;" : "+l"(d) : "l"(a), "l"(b));
}
__device__ __forceinline__ float hadd2(ull u) {
    float lo = __uint_as_float((unsigned)(u & 0xffffffffull));
    float hi = __uint_as_float((unsigned)(u >> 32));
    return lo + hi;
}
__device__ __forceinline__ float tanhfast(float x) {
    float r; asm("tanh.approx.f32 %0, %1;" : "=f"(r) : "f"(x)); return r;
}
__device__ __forceinline__ float sigfast(float x) {
    return fmaf(tanhfast(0.5f * x), 0.5f, 0.5f);
}
__device__ __forceinline__ void st_release(unsigned* p, unsigned v) {
    asm volatile("st.release.gpu.u32 [%0], %1;" :: "l"(p), "r"(v) : "memory");
}
__device__ __forceinline__ unsigned ld_acquire(unsigned* p) {
    unsigned v;
    asm volatile("ld.acquire.gpu.u32 %0, [%1];" : "=r"(v) : "l"(p) : "memory");
    return v;
}

// ---------------- kernel 0: per-launch reset (graph replays must be deterministic) ----
__global__ void init_kernel() {
    int i = blockIdx.x * blockDim.x + threadIdx.x;
    if (i < NCG) d_hflag[i].v = 0u;
    if (i < NCG * NKS) d_pflag[i].v = 0u;
    for (int j = i; j < BB * HH; j += gridDim.x * blockDim.x) d_hbuf[j] = 0.0f;  // h_0 (slot 0)
}

// ---------------- kernel 1: fused embedding gather + input GEMM (FFMA2) ---------------
// xg[(t*64+b)][n] = emb[x[b][t]] . W_ih[n] + (b_ih[n] + b_hh[n])
// 128(M) x 64(N) tile, K-tile 16 (8 k-pairs), 256 threads, 8x4 microtile.
// Smem K-contiguous so FFMA2 operands are natural LDS.64 k-pairs:
//   As[128][20] floats (10-ull row stride; a-reads are warp-broadcast, stride parity moot)
//   Bs[64][18]  floats (9-ull odd row stride; cols strided by 16 -> conflict-free b-reads)
__global__ void __launch_bounds__(256) emb_gemm_kernel(
    const int*   __restrict__ x,
    const float* __restrict__ emb,
    const float* __restrict__ W_ih,
    const float* __restrict__ b_ih,
    const float* __restrict__ b_hh)
{
    __shared__ float As[128 * 20];
    __shared__ float Bs[64 * 18];
    const int tid = threadIdx.x;
    const int m0  = blockIdx.y * 128;
    const int n0  = blockIdx.x * 64;

    // A loader: row rA = tid>>1 (0..127), k-octet kA = (tid&1)*8
    const int rA = tid >> 1, kA = (tid & 1) * 8;
    const int tpos = (m0 + rA) >> 6, bpos = rA & 63;
    const float* aptr = emb + (size_t)x[bpos * TT + tpos] * EE + kA;
    // B loader: row rB = tid>>2 (0..63), k-quad kB = (tid&3)*4
    const int rB = tid >> 2, kB = (tid & 3) * 4;
    const float* bptr = W_ih + (size_t)(n0 + rB) * EE + kB;

    const int tx = tid & 15, ty = tid >> 4;    // cols {tx+16c}, rows {ty*8+i}

    ull acc2[8][4];
#pragma unroll
    for (int i = 0; i < 8; ++i)
#pragma unroll
        for (int c = 0; c < 4; ++c) acc2[i][c] = 0ull;

    const ull* Asu = (const ull*)As;           // row stride 10 ull
    const ull* Bsu = (const ull*)Bs;           // row stride 9 ull

    for (int kt = 0; kt < EE; kt += 16) {
        float4 a0 = *(const float4*)(aptr + kt);
        float4 a1 = *(const float4*)(aptr + kt + 4);
        float4 bv = *(const float4*)(bptr + kt);
        __syncthreads();
        *(float4*)&As[rA * 20 + kA]     = a0;
        *(float4*)&As[rA * 20 + kA + 4] = a1;
        *(float2*)&Bs[rB * 18 + kB]     = make_float2(bv.x, bv.y);
        *(float2*)&Bs[rB * 18 + kB + 2] = make_float2(bv.z, bv.w);
        __syncthreads();
#pragma unroll
        for (int p = 0; p < 8; ++p) {
            ull b2[4];
#pragma unroll
            for (int c = 0; c < 4; ++c) b2[c] = Bsu[(tx + 16 * c) * 9 + p];
#pragma unroll
            for (int i = 0; i < 8; ++i) {
                ull a2 = Asu[(ty * 8 + i) * 10 + p];
                ffma2(acc2[i][0], a2, b2[0]);
                ffma2(acc2[i][1], a2, b2[1]);
                ffma2(acc2[i][2], a2, b2[2]);
                ffma2(acc2[i][3], a2, b2[3]);
            }
        }
    }

    float bias[4];
#pragma unroll
    for (int c = 0; c < 4; ++c) {
        int n = n0 + tx + 16 * c;
        bias[c] = b_ih[n] + b_hh[n];
    }
#pragma unroll
    for (int i = 0; i < 8; ++i) {
        float* dst = d_xg + (size_t)(m0 + ty * 8 + i) * GH + n0 + tx;
#pragma unroll
        for (int c = 0; c < 4; ++c)
            dst[16 * c] = hadd2(acc2[i][c]) + bias[c];
    }
}

// ---------------- kernel 2: persistent LSTM scan (padded flags, 1-thread rel/acq) -----
// CTA (cg = bid&15, ks = bid>>4): cg owns h-cols [cg*32, cg*32+32) for all 4 gates,
// ks owns k in [ks*64, ks*64+64). Thread (bg = tid>>5, rg = tid&31) computes rows
// {q*32+rg : q<4} for batches b0..b0+7. ks==0 additionally reduces + gates + writes h.
__global__ void __launch_bounds__(256, 1) scan_kernel(const float* __restrict__ W_hh) {
    extern __shared__ float sm[];
    float* sm_w = sm;                    // [128][WROW]
    float* sm_h = sm + 128 * WROW;       // [64][KC]

    const int tid = threadIdx.x;
    const int cg  = blockIdx.x & (NCG - 1);
    const int ks  = blockIdx.x >> 4;
    const int rg  = tid & 31;
    const int bg  = tid >> 5;
    const int b0  = bg * 8;

    // W_hh slice -> smem once; reused for all 512 steps.
    for (int idx = tid; idx < 128 * KC; idx += 256) {
        int r = idx >> 6, k = idx & 63;
        int grow = (r >> 5) * HH + cg * 32 + (r & 31);
        sm_w[r * WROW + k] = W_hh[(size_t)grow * HH + ks * KC + k];
    }

    float creg[8];
#pragma unroll
    for (int j = 0; j < 8; ++j) creg[j] = 0.0f;

    const ull* Ws2 = (const ull*)sm_w;   // row stride 33 ull (odd -> conflict-free)
    const ull* Hs2 = (const ull*)sm_h;   // row stride 32 ull (broadcast reads)

    for (int t = 0; t < TT; ++t) {
        // --- wait for h_t chunk producers (2 per-cg padded flags, 1 poller each) ---
        if (tid < 2) {
            unsigned* f = &d_hflag[2 * ks + tid].v;
            while (ld_acquire(f) < (unsigned)t) { }
        }
        __syncthreads();                 // also covers one-time W load at t==0

        // --- stage h_t chunk (L2-coherent loads; L1 is stale across SMs) ---
        const float* hsrc = d_hbuf + (size_t)(t & 1) * HSLOT + ks * KC;
#pragma unroll
        for (int v = 0; v < 4; ++v) {
            int fidx = tid * 16 + v * 4;
            int b = fidx >> 6, k = fidx & 63;
            float4 hv = __ldcg((const float4*)(hsrc + b * HH + k));
            *(float4*)(sm_h + b * KC + k) = hv;
        }
        __syncthreads();

        // --- prefetch xg for the reducer (independent of h; hides DRAM latency) ---
        float xr[4][8];
        if (ks == 0) {
            const float* xgp = d_xg + (size_t)t * BB * GH;
#pragma unroll
            for (int q = 0; q < 4; ++q) {
                int grow = q * HH + cg * 32 + rg;
#pragma unroll
                for (int j = 0; j < 8; ++j)
                    xr[q][j] = __ldcs(xgp + (size_t)(b0 + j) * GH + grow);
            }
        }

        // --- partial GEMV: acc[q][j] = pairwise-k  W[q*32+rg] . h[b0+j] ---
        ull acc[4][8];
#pragma unroll
        for (int q = 0; q < 4; ++q)
#pragma unroll
            for (int j = 0; j < 8; ++j) acc[q][j] = 0ull;

#pragma unroll 4
        for (int k2 = 0; k2 < 32; ++k2) {
            ull w0 = Ws2[(rg     ) * 33 + k2];
            ull w1 = Ws2[(rg + 32) * 33 + k2];
            ull w2 = Ws2[(rg + 64) * 33 + k2];
            ull w3 = Ws2[(rg + 96) * 33 + k2];
            const ull* hp = Hs2 + b0 * 32 + k2;
#pragma unroll
            for (int j = 0; j < 8; ++j) {
                ull hv = hp[j * 32];
                ffma2(acc[0][j], w0, hv);
                ffma2(acc[1][j], w1, hv);
                ffma2(acc[2][j], w2, hv);
                ffma2(acc[3][j], w3, hv);
            }
        }

        if (ks != 0) {
            // publish partial into slot t&1 (L2 stores), then single-thread release
            float* pb = d_part + (size_t)(t & 1) * PSLOT + (size_t)((cg * NKS + ks) * 128) * BB;
#pragma unroll
            for (int q = 0; q < 4; ++q) {
                float v0 = hadd2(acc[q][0]), v1 = hadd2(acc[q][1]);
                float v2 = hadd2(acc[q][2]), v3 = hadd2(acc[q][3]);
                float v4 = hadd2(acc[q][4]), v5 = hadd2(acc[q][5]);
                float v6 = hadd2(acc[q][6]), v7 = hadd2(acc[q][7]);
                float* dst = pb + (q * 32 + rg) * BB + b0;
                __stcg((float4*)(dst),     make_float4(v0, v1, v2, v3));
                __stcg((float4*)(dst + 4), make_float4(v4, v5, v6, v7));
            }
            __syncthreads();
            if (tid == 0) st_release(&d_pflag[cg * NKS + ks].v, (unsigned)(t + 1));
        } else {
            float gp[4][8];
#pragma unroll
            for (int q = 0; q < 4; ++q)
#pragma unroll
                for (int j = 0; j < 8; ++j) gp[q][j] = hadd2(acc[q][j]) + xr[q][j];

            // wait for the 7 sibling partials (7 padded flags, 1 poller each)
            if (tid < 7) {
                unsigned* f = &d_pflag[cg * NKS + 1 + tid].v;
                while (ld_acquire(f) < (unsigned)(t + 1)) { }
            }
            __syncthreads();

            const float* ps = d_part + (size_t)(t & 1) * PSLOT;
            for (int k = 1; k < NKS; ++k) {
                const float* pb = ps + (size_t)((cg * NKS + k) * 128) * BB;
#pragma unroll
                for (int q = 0; q < 4; ++q) {
                    const float4* p = (const float4*)(pb + (q * 32 + rg) * BB + b0);
                    float4 u0 = __ldcg(p);
                    float4 u1 = __ldcg(p + 1);
                    gp[q][0] += u0.x; gp[q][1] += u0.y; gp[q][2] += u0.z; gp[q][3] += u0.w;
                    gp[q][4] += u1.x; gp[q][5] += u1.y; gp[q][6] += u1.z; gp[q][7] += u1.w;
                }
            }

            // gates (HW tanh), cell update, write h_{t+1} into slot (t+1)&1
            float* hdst = d_hbuf + (size_t)((t + 1) & 1) * HSLOT;
            const int col = cg * 32 + rg;
#pragma unroll
            for (int j = 0; j < 8; ++j) {
                float ig = sigfast(gp[0][j]);
                float fg = sigfast(gp[1][j]);
                float gg = tanhfast(gp[2][j]);
                float og = sigfast(gp[3][j]);
                creg[j] = fg * creg[j] + ig * gg;
                __stcg(hdst + (b0 + j) * HH + col, og * tanhfast(creg[j]));
            }
            __syncthreads();
            if (tid == 0) st_release(&d_hflag[cg].v, (unsigned)(t + 1));
        }
    }
}

// ---------------- kernel 3: final FC (64x4x512) ----------------------------------------
__global__ void fc_kernel(const float* __restrict__ W_fc,
                          const float* __restrict__ b_fc,
                          float* __restrict__ out)
{
    const int b    = blockIdx.x;
    const int w    = threadIdx.x >> 5;   // class 0..3
    const int lane = threadIdx.x & 31;
    const float* hb = d_hbuf + (size_t)(TT & 1) * HSLOT + b * HH;  // h_512 lives in slot 0
    const float* wf = W_fc + w * HH;
    float s = 0.0f;
    for (int k = lane; k < HH; k += 32) s += hb[k] * wf[k];
#pragma unroll
    for (int o = 16; o; o >>= 1) s += __shfl_down_sync(0xffffffffu, s, o);
    if (lane == 0) out[b * CD + w] = s + b_fc[w];
}

// ---------------- host launcher ---------------------------------------------------------
extern "C" void kernel_launch(void* const* d_in, const int* in_sizes, int n_in,
                              void* d_out, int out_size) {
    const int*   x    = (const int*)  d_in[0];
    const float* emb  = (const float*)d_in[1];
    const float* W_ih = (const float*)d_in[2];
    const float* W_hh = (const float*)d_in[3];
    const float* b_ih = (const float*)d_in[4];
    const float* b_hh = (const float*)d_in[5];
    const float* W_fc = (const float*)d_in[6];
    const float* b_fc = (const float*)d_in[7];
    float* out = (float*)d_out;

    cudaFuncSetAttribute(scan_kernel, cudaFuncAttributeMaxDynamicSharedMemorySize, SMEM_SCAN);

    init_kernel<<<64, 256>>>();
    emb_gemm_kernel<<<dim3(GH / 64, (BB * TT) / 128), 256>>>(x, emb, W_ih, b_ih, b_hh);
    scan_kernel<<<GRID_SCAN, 256, SMEM_SCAN>>>(W_hh);
    fc_kernel<<<BB, 128>>>(W_fc, b_fc, out);
}

// round 13
// speedup vs baseline: 2.1715x; 1.8902x over previous
#include <cuda_runtime.h>
#include <cstdint>

// ---------------- problem constants ----------------
#define BB   64      // batch
#define TT   512     // seq len
#define EE   256     // embed dim
#define HH   512     // hidden
#define GH   2048    // 4*H
#define CD   4       // classes

// ---------------- scan configuration ----------------
#define NCG  16                 // column groups (32 h-cols each, all 4 gates)
#define NKS  8                  // k splits (64 k each) == batch-octet reducers
#define GRID_SCAN (NCG * NKS)   // 128 persistent CTAs, 1 per SM
#define KC   64                 // k per chunk
#define WROW 66                 // padded W smem row (floats) = 33 ull (odd -> conflict-free LDS.64)
#define SMEM_SCAN ((128 * WROW + BB * KC) * 4)   // 50176 B dynamic smem

typedef unsigned long long ull;

#define PSLOT ((size_t)NCG * NKS * BB * 128)     // floats per partial slot
#define HSLOT ((size_t)BB * HH)                  // floats per h slot

// ---------------- device scratch (no allocs allowed) ----------------
// Each flag on its OWN 256B line (same-address L2 contention kills spin flags).
struct alignas(256) PadFlag { unsigned v; unsigned pad[63]; };

__device__ float   d_xg[(size_t)TT * BB * GH];        // 256 MB: xg[(t*64+b)*2048 + g]
__device__ float   d_hbuf[2 * BB * HH];               // double-buffered h: slot t&1 holds h_t
__device__ float   d_part[2 * NCG * NKS * BB * 128];  // 8 MB: [slot][cg][src][b][row]
__device__ PadFlag d_hflag[NCG * NKS];                // v=t+1: (cg,ks) wrote its h_{t+1} batches
__device__ PadFlag d_pflag[NCG * NKS];                // v=t+1: (cg,ks) published step-t partial

// ---------------- helpers ----------------
__device__ __forceinline__ void ffma2(ull& d, ull a, ull b) {
    asm("fma.rn.f32x2 %0, %1, %2, %0;" : "+l"(d) : "l"(a), "l"(b));
}
__device__ __forceinline__ float hadd2(ull u) {
    float lo = __uint_as_float((unsigned)(u & 0xffffffffull));
    float hi = __uint_as_float((unsigned)(u >> 32));
    return lo + hi;
}
__device__ __forceinline__ float tanhfast(float x) {
    float r; asm("tanh.approx.f32 %0, %1;" : "=f"(r) : "f"(x)); return r;
}
__device__ __forceinline__ float sigfast(float x) {
    return fmaf(tanhfast(0.5f * x), 0.5f, 0.5f);
}
__device__ __forceinline__ void st_release(unsigned* p, unsigned v) {
    asm volatile("st.release.gpu.u32 [%0], %1;" :: "l"(p), "r"(v) : "memory");
}
__device__ __forceinline__ unsigned ld_acquire(unsigned* p) {
    unsigned v;
    asm volatile("ld.acquire.gpu.u32 %0, [%1];" : "=r"(v) : "l"(p) : "memory");
    return v;
}

// ---------------- kernel 0: per-launch reset (graph replays must be deterministic) ----
__global__ void init_kernel() {
    int i = blockIdx.x * blockDim.x + threadIdx.x;
    if (i < NCG * NKS) { d_hflag[i].v = 0u; d_pflag[i].v = 0u; }
    for (int j = i; j < BB * HH; j += gridDim.x * blockDim.x) d_hbuf[j] = 0.0f;  // h_0 (slot 0)
}

// ---------------- kernel 1: fused embedding gather + input GEMM (FFMA2) ---------------
// xg[(t*64+b)][n] = emb[x[b][t]] . W_ih[n] + (b_ih[n] + b_hh[n])
// 128(M) x 64(N) tile, K-tile 16 (8 k-pairs), 256 threads, 8x4 microtile.
__global__ void __launch_bounds__(256) emb_gemm_kernel(
    const int*   __restrict__ x,
    const float* __restrict__ emb,
    const float* __restrict__ W_ih,
    const float* __restrict__ b_ih,
    const float* __restrict__ b_hh)
{
    __shared__ float As[128 * 20];
    __shared__ float Bs[64 * 18];
    const int tid = threadIdx.x;
    const int m0  = blockIdx.y * 128;
    const int n0  = blockIdx.x * 64;

    const int rA = tid >> 1, kA = (tid & 1) * 8;
    const int tpos = (m0 + rA) >> 6, bpos = rA & 63;
    const float* aptr = emb + (size_t)x[bpos * TT + tpos] * EE + kA;
    const int rB = tid >> 2, kB = (tid & 3) * 4;
    const float* bptr = W_ih + (size_t)(n0 + rB) * EE + kB;

    const int tx = tid & 15, ty = tid >> 4;

    ull acc2[8][4];
#pragma unroll
    for (int i = 0; i < 8; ++i)
#pragma unroll
        for (int c = 0; c < 4; ++c) acc2[i][c] = 0ull;

    const ull* Asu = (const ull*)As;           // row stride 10 ull
    const ull* Bsu = (const ull*)Bs;           // row stride 9 ull

    for (int kt = 0; kt < EE; kt += 16) {
        float4 a0 = *(const float4*)(aptr + kt);
        float4 a1 = *(const float4*)(aptr + kt + 4);
        float4 bv = *(const float4*)(bptr + kt);
        __syncthreads();
        *(float4*)&As[rA * 20 + kA]     = a0;
        *(float4*)&As[rA * 20 + kA + 4] = a1;
        *(float2*)&Bs[rB * 18 + kB]     = make_float2(bv.x, bv.y);
        *(float2*)&Bs[rB * 18 + kB + 2] = make_float2(bv.z, bv.w);
        __syncthreads();
#pragma unroll
        for (int p = 0; p < 8; ++p) {
            ull b2[4];
#pragma unroll
            for (int c = 0; c < 4; ++c) b2[c] = Bsu[(tx + 16 * c) * 9 + p];
#pragma unroll
            for (int i = 0; i < 8; ++i) {
                ull a2 = Asu[(ty * 8 + i) * 10 + p];
                ffma2(acc2[i][0], a2, b2[0]);
                ffma2(acc2[i][1], a2, b2[1]);
                ffma2(acc2[i][2], a2, b2[2]);
                ffma2(acc2[i][3], a2, b2[3]);
            }
        }
    }

    float bias[4];
#pragma unroll
    for (int c = 0; c < 4; ++c) {
        int n = n0 + tx + 16 * c;
        bias[c] = b_ih[n] + b_hh[n];
    }
#pragma unroll
    for (int i = 0; i < 8; ++i) {
        float* dst = d_xg + (size_t)(m0 + ty * 8 + i) * GH + n0 + tx;
#pragma unroll
        for (int c = 0; c < 4; ++c)
            dst[16 * c] = hadd2(acc2[i][c]) + bias[c];
    }
}

// ---------------- kernel 2: persistent LSTM scan, distributed reduction ----------------
// CTA (cg = bid&15, ks = bid>>4):
//   GEMV role: rows {q*32+rg : q<4} of cols [cg*32, cg*32+32), k in [ks*64, ks*64+64),
//              all 64 batches (thread: rg=tid&31, bg=tid>>5, acc[4][8]).
//   Reduce role: batches [ks*8, ks*8+8) x its 32 cols; thread (bj=tid>>5, c=tid&31)
//              owns (b=ks*8+bj, col=cg*32+c), keeps cell state creg in a register.
// Partial layout: d_part[slot][cg][src][b][row] -> publish & reduce both coalesced.
__global__ void __launch_bounds__(256, 1) scan_kernel(const float* __restrict__ W_hh) {
    extern __shared__ float sm[];
    float* sm_w = sm;                    // [128][WROW]
    float* sm_h = sm + 128 * WROW;       // [64][KC]

    const int tid = threadIdx.x;
    const int cg  = blockIdx.x & (NCG - 1);
    const int ks  = blockIdx.x >> 4;
    const int rg  = tid & 31;
    const int bg  = tid >> 5;
    const int b0  = bg * 8;
    const int bj  = tid >> 5;            // reduce: batch-in-octet
    const int c   = tid & 31;            // reduce: col-in-group
    const int bred = ks * 8 + bj;        // reduce: owned batch
    const int colred = cg * 32 + c;      // reduce: owned column

    // W_hh slice -> smem once; reused for all 512 steps.
    for (int idx = tid; idx < 128 * KC; idx += 256) {
        int r = idx >> 6, k = idx & 63;
        int grow = (r >> 5) * HH + cg * 32 + (r & 31);
        sm_w[r * WROW + k] = W_hh[(size_t)grow * HH + ks * KC + k];
    }

    float creg = 0.0f;                   // cell state for (bred, colred)

    const ull* Ws2 = (const ull*)sm_w;   // row stride 33 ull (odd -> conflict-free)
    const ull* Hs2 = (const ull*)sm_h;   // row stride 32 ull (broadcast reads)

    for (int t = 0; t < TT; ++t) {
        // --- wait for the 16 producers of the h_t cols/batches we consume ---
        if (tid < 16) {
            int cgp = 2 * ks + (tid >> 3);          // the 2 cgs whose cols we read
            int src = tid & 7;                      // each cg has 8 batch-owners
            unsigned* f = &d_hflag[cgp * NKS + src].v;
            while (ld_acquire(f) < (unsigned)t) { }
        }
        __syncthreads();                 // also covers one-time W load at t==0

        // --- stage h_t chunk (L2-coherent; L1 stale across SMs) ---
        const float* hsrc = d_hbuf + (size_t)(t & 1) * HSLOT + ks * KC;
#pragma unroll
        for (int v = 0; v < 4; ++v) {
            int fidx = tid * 16 + v * 4;
            int b = fidx >> 6, k = fidx & 63;
            float4 hv = __ldcg((const float4*)(hsrc + b * HH + k));
            *(float4*)(sm_h + b * KC + k) = hv;
        }

        // --- prefetch xg for OUR reduce outputs (independent of h) ---
        float xr[4];
        {
            const float* xgp = d_xg + ((size_t)t * BB + bred) * GH;
#pragma unroll
            for (int q = 0; q < 4; ++q)
                xr[q] = __ldcs(xgp + q * HH + colred);
        }
        __syncthreads();

        // --- partial GEMV: acc[q][j] = pairwise-k  W[q*32+rg] . h[b0+j] ---
        ull acc[4][8];
#pragma unroll
        for (int q = 0; q < 4; ++q)
#pragma unroll
            for (int j = 0; j < 8; ++j) acc[q][j] = 0ull;

#pragma unroll 4
        for (int k2 = 0; k2 < 32; ++k2) {
            ull w0 = Ws2[(rg     ) * 33 + k2];
            ull w1 = Ws2[(rg + 32) * 33 + k2];
            ull w2 = Ws2[(rg + 64) * 33 + k2];
            ull w3 = Ws2[(rg + 96) * 33 + k2];
            const ull* hp = Hs2 + b0 * 32 + k2;
#pragma unroll
            for (int j = 0; j < 8; ++j) {
                ull hv = hp[j * 32];
                ffma2(acc[0][j], w0, hv);
                ffma2(acc[1][j], w1, hv);
                ffma2(acc[2][j], w2, hv);
                ffma2(acc[3][j], w3, hv);
            }
        }

        // --- publish partials: [cg][src=ks][b][row], STG.32 coalesced over rg ---
        {
            float* pb = d_part + (size_t)(t & 1) * PSLOT
                      + (size_t)((cg * NKS + ks) * BB) * 128;
#pragma unroll
            for (int j = 0; j < 8; ++j) {
                float* row = pb + (size_t)(b0 + j) * 128 + rg;
                __stcg(row      , hadd2(acc[0][j]));
                __stcg(row + 32 , hadd2(acc[1][j]));
                __stcg(row + 64 , hadd2(acc[2][j]));
                __stcg(row + 96 , hadd2(acc[3][j]));
            }
        }
        __syncthreads();
        if (tid == 0) st_release(&d_pflag[cg * NKS + ks].v, (unsigned)(t + 1));

        // --- wait for all 8 k-slices of our cg ---
        if (tid < 8) {
            unsigned* f = &d_pflag[cg * NKS + tid].v;
            while (ld_acquire(f) < (unsigned)(t + 1)) { }
        }
        __syncthreads();

        // --- reduce 8 slabs for (bred, colred): 32 coalesced LDG.32, one MLP wave ---
        float g0 = xr[0], g1 = xr[1], g2 = xr[2], g3 = xr[3];
        {
            const float* ps = d_part + (size_t)(t & 1) * PSLOT;
#pragma unroll
            for (int src = 0; src < NKS; ++src) {
                const float* row = ps + (size_t)((cg * NKS + src) * BB + bred) * 128 + c;
                g0 += __ldcg(row);
                g1 += __ldcg(row + 32);
                g2 += __ldcg(row + 64);
                g3 += __ldcg(row + 96);
            }
        }

        // --- gates, cell update, write our h_{t+1} element ---
        {
            float ig = sigfast(g0);
            float fg = sigfast(g1);
            float gg = tanhfast(g2);
            float og = sigfast(g3);
            creg = fg * creg + ig * gg;
            float* hdst = d_hbuf + (size_t)((t + 1) & 1) * HSLOT;
            __stcg(hdst + (size_t)bred * HH + colred, og * tanhfast(creg));
        }
        __syncthreads();
        if (tid == 0) st_release(&d_hflag[cg * NKS + ks].v, (unsigned)(t + 1));
    }
}

// ---------------- kernel 3: final FC (64x4x512) ----------------------------------------
__global__ void fc_kernel(const float* __restrict__ W_fc,
                          const float* __restrict__ b_fc,
                          float* __restrict__ out)
{
    const int b    = blockIdx.x;
    const int w    = threadIdx.x >> 5;   // class 0..3
    const int lane = threadIdx.x & 31;
    const float* hb = d_hbuf + (size_t)(TT & 1) * HSLOT + b * HH;  // h_512 lives in slot 0
    const float* wf = W_fc + w * HH;
    float s = 0.0f;
    for (int k = lane; k < HH; k += 32) s += hb[k] * wf[k];
#pragma unroll
    for (int o = 16; o; o >>= 1) s += __shfl_down_sync(0xffffffffu, s, o);
    if (lane == 0) out[b * CD + w] = s + b_fc[w];
}

// ---------------- host launcher ---------------------------------------------------------
extern "C" void kernel_launch(void* const* d_in, const int* in_sizes, int n_in,
                              void* d_out, int out_size) {
    const int*   x    = (const int*)  d_in[0];
    const float* emb  = (const float*)d_in[1];
    const float* W_ih = (const float*)d_in[2];
    const float* W_hh = (const float*)d_in[3];
    const float* b_ih = (const float*)d_in[4];
    const float* b_hh = (const float*)d_in[5];
    const float* W_fc = (const float*)d_in[6];
    const float* b_fc = (const float*)d_in[7];
    float* out = (float*)d_out;

    cudaFuncSetAttribute(scan_kernel, cudaFuncAttributeMaxDynamicSharedMemorySize, SMEM_SCAN);

    init_kernel<<<64, 256>>>();
    emb_gemm_kernel<<<dim3(GH / 64, (BB * TT) / 128), 256>>>(x, emb, W_ih, b_ih, b_hh);
    scan_kernel<<<GRID_SCAN, 256, SMEM_SCAN>>>(W_hh);
    fc_kernel<<<BB, 128>>>(W_fc, b_fc, out);
}